// round 14
// baseline (speedup 1.0000x reference)
#include <cuda_runtime.h>
#include <cuda_fp16.h>
#include <cstdint>

// ---------------------------------------------------------------------------
// Problem constants
// ---------------------------------------------------------------------------
#define OUTF 4096
#define INF  11008
#define MDIM 4096                 // 2*2048 tokens
#define NDIM OUTF
#define KDIM INF
#define NVEC (OUTF * (INF / 8))   // 5,636,096 code vectors

// GEMM tiling
#define BM 128
#define BN 128
#define BK 32                     // packing granularity (per gmem tile)
#define KT (KDIM / BK)            // 344 packed k-tiles
#define KTH (KT / 2)              // 172 k-tiles per K-half
#define KIT_H (KTH / 2)           // 86 mainloop iterations per half (64-k each)
#define MT (MDIM / BM)            // 32
#define NT (NDIM / BN)            // 32

#define TILE_G 8192               // packed gmem tile: 128 rows x 64B (linear)
#define TILE_S 8192               // smem tile: 128 rows x 64B (XOR-swizzled)
#define NST 3
#define STAGE_BYTES (4 * TILE_S)  // 32768 (A0, A1, W0, W1 — two k-tiles)
#define SMEM_TOTAL (NST * STAGE_BYTES)   // 98304 -> 2 CTAs/SM

// Packed fp16 operand tiles + K-split partial buffer (static: alloc-guard safe)
__device__ __align__(256) uint8_t g_a16[(size_t)MT * KT * TILE_G];
__device__ __align__(256) uint8_t g_w16[(size_t)NT * KT * TILE_G];
__device__ __align__(256) float   g_part[(size_t)MDIM * NDIM];

// ---------------------------------------------------------------------------
// PTX helpers (plain sm_80+ — compile at compute_103)
// ---------------------------------------------------------------------------
__device__ __forceinline__ uint32_t smem_u32(const void* p) {
    uint32_t a;
    asm("{ .reg .u64 t; cvta.to.shared.u64 t, %1; cvt.u32.u64 %0, t; }"
        : "=r"(a) : "l"(p));
    return a;
}

__device__ __forceinline__ void cp_async16(uint32_t sdst, const void* gsrc) {
    asm volatile("cp.async.cg.shared.global [%0], [%1], 16;"
                 :: "r"(sdst), "l"(gsrc) : "memory");
}
#define CP_COMMIT()  asm volatile("cp.async.commit_group;" ::: "memory")
#define CP_WAIT(n)   asm volatile("cp.async.wait_group %0;" :: "n"(n) : "memory")

__device__ __forceinline__ void ldsm4(uint32_t (&r)[4], uint32_t addr) {
    asm volatile("ldmatrix.sync.aligned.m8n8.x4.shared.b16 {%0,%1,%2,%3}, [%4];"
                 : "=r"(r[0]), "=r"(r[1]), "=r"(r[2]), "=r"(r[3]) : "r"(addr));
}

__device__ __forceinline__ void mma_f16(float (&c)[4], const uint32_t (&a)[4],
                                        uint32_t b0, uint32_t b1) {
    asm volatile(
        "mma.sync.aligned.m16n8k16.row.col.f32.f16.f16.f32 "
        "{%0,%1,%2,%3}, {%4,%5,%6,%7}, {%8,%9}, {%0,%1,%2,%3};"
        : "+f"(c[0]), "+f"(c[1]), "+f"(c[2]), "+f"(c[3])
        : "r"(a[0]), "r"(a[1]), "r"(a[2]), "r"(a[3]), "r"(b0), "r"(b1));
}

// ---------------------------------------------------------------------------
// Kernel 1: x (fp32 row-major) -> packed A16 fp16 tiles (linear 128x64B)
// ---------------------------------------------------------------------------
__global__ void convert_x_kernel(const float* __restrict__ x) {
    int i = blockIdx.x * blockDim.x + threadIdx.x;    // one thread = 8 k-elems
    if (i >= MDIM * (KDIM / 8)) return;
    int m = i / (KDIM / 8);
    int k = (i % (KDIM / 8)) * 8;

    const float4* xp = reinterpret_cast<const float4*>(x + (size_t)m * KDIM + k);
    float4 v0 = xp[0], v1 = xp[1];
    float v[8] = {v0.x, v0.y, v0.z, v0.w, v1.x, v1.y, v1.z, v1.w};

    uint32_t h[4];
    #pragma unroll
    for (int e = 0; e < 4; e++) {
        __half h0 = __float2half_rn(v[2 * e]);
        __half h1 = __float2half_rn(v[2 * e + 1]);
        h[e] = (uint32_t)__half_as_ushort(h0) | ((uint32_t)__half_as_ushort(h1) << 16);
    }

    int mt = m >> 7, r = m & 127, kt = k >> 5, c = (k & 31) >> 3;
    size_t off = ((size_t)mt * KT + kt) * TILE_G + r * 64 + c * 16;
    *reinterpret_cast<uint4*>(g_a16 + off) = make_uint4(h[0], h[1], h[2], h[3]);
}

// ---------------------------------------------------------------------------
// Kernel 2: dequant -> packed W16 fp16 tiles (linear 128x64B)
// ---------------------------------------------------------------------------
__global__ void dequant_kernel(const int* __restrict__ indices,
                               const float* __restrict__ codebook,
                               const float* __restrict__ scales) {
    int i = blockIdx.x * blockDim.x + threadIdx.x;    // one thread = one 8-vector
    if (i >= NVEC) return;
    int n = i / (INF / 8);
    int k = (i % (INF / 8)) * 8;

    int code = indices[i];
    const float4* cb = reinterpret_cast<const float4*>(codebook) + (size_t)code * 2;
    float4 c0 = cb[0], c1 = cb[1];
    float s = __ldg(&scales[n]);
    float v[8] = {c0.x * s, c0.y * s, c0.z * s, c0.w * s,
                  c1.x * s, c1.y * s, c1.z * s, c1.w * s};

    uint32_t h[4];
    #pragma unroll
    for (int e = 0; e < 4; e++) {
        __half h0 = __float2half_rn(v[2 * e]);
        __half h1 = __float2half_rn(v[2 * e + 1]);
        h[e] = (uint32_t)__half_as_ushort(h0) | ((uint32_t)__half_as_ushort(h1) << 16);
    }

    int nt = n >> 7, r = n & 127, kt = k >> 5, c = (k & 31) >> 3;
    size_t off = ((size_t)nt * KT + kt) * TILE_G + r * 64 + c * 16;
    *reinterpret_cast<uint4*>(g_w16 + off) = make_uint4(h[0], h[1], h[2], h[3]);
}

// ---------------------------------------------------------------------------
// Kernel 3: fp16 HMMA GEMM, K-split 2x in one launch (grid 2048):
//   half 0: C_tile = A·Wᵀ over k-tiles [0,172)    -> writes C
//   half 1: P_tile = A·Wᵀ over k-tiles [172,344)  -> writes g_part
// 128x128 CTA, 64-k pipeline stages, NST=3, XOR-swizzled smem, 2 CTAs/SM.
// smem swizzle: byte = row*64 + (c ^ ((row>>1)&3))*16
// ---------------------------------------------------------------------------
__global__ void __launch_bounds__(256, 2)
gemm_kernel(float* __restrict__ C) {
    extern __shared__ __align__(1024) uint8_t smem[];
    const uint32_t sb = smem_u32(smem);
    const int tid = threadIdx.x;
    const int lane = tid & 31;
    const int wid = tid >> 5;
    const int wm = wid & 3;       // 4 m-warps (32 rows each)
    const int wn = wid >> 2;      // 2 n-warps (64 cols each)

    // decode: half (K range) + grouped raster (8 m-tiles/group for L2 reuse)
    const int bid0 = blockIdx.x;
    const int half = bid0 >> 10;            // 0 or 1
    const int bid = bid0 & 1023;
    const int mt = (bid >> 8) * 8 + (bid & 7);
    const int nt = (bid >> 3) & 31;
    const int kbase = half * KTH;           // k-tile offset

    const uint8_t* gA = g_a16 + (size_t)mt * KT * TILE_G;
    const uint8_t* gW = g_w16 + (size_t)nt * KT * TILE_G;

    // stage layout: [A(2k) | A(2k+1) | W(2k) | W(2k+1)], 8KB each.
    auto load_stage = [&](int s, int it) {
        #pragma unroll
        for (int j = 0; j < 8; j++) {
            int ch = tid + j * 256;
            int quad = ch >> 9;              // 0:A0 1:A1 2:W0 3:W1
            int row = (ch & 511) >> 2;
            int c = ch & 3;
            int cs = c ^ ((row >> 1) & 3);
            int ktile = kbase + 2 * it + (quad & 1);
            const uint8_t* gsrc = ((quad < 2) ? gA : gW) + (size_t)ktile * TILE_G
                                  + row * 64 + c * 16;
            uint32_t sdst = sb + s * STAGE_BYTES + quad * TILE_S
                            + row * 64 + cs * 16;
            cp_async16(sdst, gsrc);
        }
    };

    // prologue: fill NST-1 stages
    #pragma unroll
    for (int s = 0; s < NST - 1; s++) {
        load_stage(s, s);
        CP_COMMIT();
    }
    CP_WAIT(NST - 2);
    __syncthreads();

    float acc[2][8][4];
    #pragma unroll
    for (int mi = 0; mi < 2; mi++)
        #pragma unroll
        for (int n8 = 0; n8 < 8; n8++)
            #pragma unroll
            for (int q = 0; q < 4; q++) acc[mi][n8][q] = 0.0f;

    // per-thread ldmatrix addressing (swizzle select constant per thread)
    const int hb = lane >> 4;                 // 16B half select
    const int rA = (lane & 15);
    const int selA = (rA >> 1) & 3;
    const uint32_t a_row_off = (uint32_t)(wm * 32 + rA) * 64;
    const uint32_t w_row_off = (uint32_t)(wn * 64 + rA) * 64;
    const uint32_t ck0 = (uint32_t)(((0 * 2 + hb) ^ selA) * 16);   // kh=0
    const uint32_t ck1 = (uint32_t)(((1 * 2 + hb) ^ selA) * 16);   // kh=1

    // interleaved sub-step: A ldsm burst, then per-ni (W ldsm -> 8 MMAs)
    auto sub_step = [&](uint32_t sA, uint32_t sW) {
        uint32_t a16[2][2][4], wr[4][2][4];
        #pragma unroll
        for (int mi = 0; mi < 2; mi++) {
            ldsm4(a16[mi][0], sA + a_row_off + mi * 1024 + ck0);
            ldsm4(a16[mi][1], sA + a_row_off + mi * 1024 + ck1);
        }
        #pragma unroll
        for (int ni = 0; ni < 4; ni++) {
            ldsm4(wr[ni][0], sW + w_row_off + ni * 1024 + ck0);
            ldsm4(wr[ni][1], sW + w_row_off + ni * 1024 + ck1);
            #pragma unroll
            for (int kh = 0; kh < 2; kh++)
                #pragma unroll
                for (int mi = 0; mi < 2; mi++)
                    #pragma unroll
                    for (int j = 0; j < 2; j++)
                        mma_f16(acc[mi][2 * ni + j], a16[mi][kh],
                                wr[ni][kh][j], wr[ni][kh][2 + j]);
        }
    };

    int stage = 0;
    for (int it = 0; it < KIT_H; it++) {
        const uint32_t st = sb + stage * STAGE_BYTES;

        sub_step(st, st + 2 * TILE_S);

        const int in_ = it + NST - 1;
        if (in_ < KIT_H) {
            int sn = stage + NST - 1;
            if (sn >= NST) sn -= NST;
            load_stage(sn, in_);
        }
        CP_COMMIT();

        sub_step(st + TILE_S, st + 3 * TILE_S);

        CP_WAIT(NST - 2);
        __syncthreads();
        if (++stage == NST) stage = 0;
    }

    // epilogue: fragment -> gmem (fp32); half 0 -> C, half 1 -> g_part
    float* dst = half ? g_part : C;
    const int row0 = mt * BM + wm * 32 + (lane >> 2);
    const int col0 = nt * BN + wn * 64 + (lane & 3) * 2;
    #pragma unroll
    for (int mi = 0; mi < 2; mi++) {
        #pragma unroll
        for (int n8 = 0; n8 < 8; n8++) {
            float* p0 = dst + (size_t)(row0 + mi * 16) * NDIM + col0 + n8 * 8;
            float* p1 = dst + (size_t)(row0 + mi * 16 + 8) * NDIM + col0 + n8 * 8;
            p0[0] = acc[mi][n8][0];
            p0[1] = acc[mi][n8][1];
            p1[0] = acc[mi][n8][2];
            p1[1] = acc[mi][n8][3];
        }
    }
}

// ---------------------------------------------------------------------------
// Kernel 4: C += g_part  (vectorized, pure bandwidth ~201 MB)
// ---------------------------------------------------------------------------
__global__ void reduce_kernel(float* __restrict__ C) {
    int i = blockIdx.x * blockDim.x + threadIdx.x;    // float4 index
    float4 a = reinterpret_cast<float4*>(C)[i];
    float4 b = reinterpret_cast<const float4*>(g_part)[i];
    a.x += b.x; a.y += b.y; a.z += b.z; a.w += b.w;
    reinterpret_cast<float4*>(C)[i] = a;
}

// ---------------------------------------------------------------------------
// Launch: convert -> dequant -> gemm(2048) -> reduce  (graph-capturable)
// Inputs (metadata order): x fp32, indices int32, codebook fp32, scales fp32
// ---------------------------------------------------------------------------
extern "C" void kernel_launch(void* const* d_in, const int* in_sizes, int n_in,
                              void* d_out, int out_size) {
    const float* x        = (const float*)d_in[0];
    const int*   indices  = (const int*)d_in[1];
    const float* codebook = (const float*)d_in[2];
    const float* scales   = (const float*)d_in[3];
    float* out = (float*)d_out;

    convert_x_kernel<<<(MDIM * (KDIM / 8) + 255) / 256, 256>>>(x);
    dequant_kernel<<<(NVEC + 255) / 256, 256>>>(indices, codebook, scales);

    cudaFuncSetAttribute(gemm_kernel, cudaFuncAttributeMaxDynamicSharedMemorySize,
                         SMEM_TOTAL);
    gemm_kernel<<<2 * MT * NT, 256, SMEM_TOTAL>>>(out);

    reduce_kernel<<<(MDIM * NDIM / 4) / 256, 256>>>(out);
}

// round 15
// speedup vs baseline: 1.0546x; 1.0546x over previous
#include <cuda_runtime.h>
#include <cuda_fp16.h>
#include <cstdint>

// ---------------------------------------------------------------------------
// Problem constants
// ---------------------------------------------------------------------------
#define OUTF 4096
#define INF  11008
#define MDIM 4096                 // 2*2048 tokens
#define NDIM OUTF
#define KDIM INF
#define NVEC (OUTF * (INF / 8))   // 5,636,096 code vectors
#define NBLK_CONV (MDIM * (KDIM / 8) / 256)   // 22016
#define NBLK_DEQ  (NVEC / 256)                // 22016

// GEMM tiling
#define BM 128
#define BN 128
#define BK 32                     // packing granularity (per gmem tile)
#define KT (KDIM / BK)            // 344 packed k-tiles
#define KIT (KT / 2)              // 172 mainloop iterations (64-k per stage)
#define MT (MDIM / BM)            // 32
#define NT (NDIM / BN)            // 32

#define TILE_G 8192               // packed gmem tile: 128 rows x 64B (linear)
#define TILE_S 8192               // smem tile: 128 rows x 64B (XOR-swizzled)
#define NST 3
#define STAGE_BYTES (4 * TILE_S)  // 32768 (A0, A1, W0, W1 — two k-tiles)
#define SMEM_TOTAL (NST * STAGE_BYTES)   // 98304 -> 2 CTAs/SM

// Packed fp16 operand tiles (static device arrays: alloc-guard safe)
__device__ __align__(256) uint8_t g_a16[(size_t)MT * KT * TILE_G];
__device__ __align__(256) uint8_t g_w16[(size_t)NT * KT * TILE_G];

// ---------------------------------------------------------------------------
// PTX helpers (plain sm_80+ — compile at compute_103)
// ---------------------------------------------------------------------------
__device__ __forceinline__ uint32_t smem_u32(const void* p) {
    uint32_t a;
    asm("{ .reg .u64 t; cvta.to.shared.u64 t, %1; cvt.u32.u64 %0, t; }"
        : "=r"(a) : "l"(p));
    return a;
}

__device__ __forceinline__ void cp_async16(uint32_t sdst, const void* gsrc) {
    asm volatile("cp.async.cg.shared.global [%0], [%1], 16;"
                 :: "r"(sdst), "l"(gsrc) : "memory");
}
#define CP_COMMIT()  asm volatile("cp.async.commit_group;" ::: "memory")
#define CP_WAIT(n)   asm volatile("cp.async.wait_group %0;" :: "n"(n) : "memory")

__device__ __forceinline__ void ldsm4(uint32_t (&r)[4], uint32_t addr) {
    asm volatile("ldmatrix.sync.aligned.m8n8.x4.shared.b16 {%0,%1,%2,%3}, [%4];"
                 : "=r"(r[0]), "=r"(r[1]), "=r"(r[2]), "=r"(r[3]) : "r"(addr));
}

__device__ __forceinline__ void mma_f16(float (&c)[4], const uint32_t (&a)[4],
                                        uint32_t b0, uint32_t b1) {
    asm volatile(
        "mma.sync.aligned.m16n8k16.row.col.f32.f16.f16.f32 "
        "{%0,%1,%2,%3}, {%4,%5,%6,%7}, {%8,%9}, {%0,%1,%2,%3};"
        : "+f"(c[0]), "+f"(c[1]), "+f"(c[2]), "+f"(c[3])
        : "r"(a[0]), "r"(a[1]), "r"(a[2]), "r"(a[3]), "r"(b0), "r"(b1));
}

// ---------------------------------------------------------------------------
// Kernel 1 (fused prep): blocks [0, NBLK_CONV) convert x -> A16 tiles;
// blocks [NBLK_CONV, NBLK_CONV+NBLK_DEQ) dequant -> W16 tiles.
// Both halves are DRAM-bound; fusing overlaps their traffic.
// ---------------------------------------------------------------------------
__global__ void prep_kernel(const float* __restrict__ x,
                            const int* __restrict__ indices,
                            const float* __restrict__ codebook,
                            const float* __restrict__ scales) {
    if (blockIdx.x < NBLK_CONV) {
        // ---- convert x ----
        int i = blockIdx.x * 256 + threadIdx.x;       // one thread = 8 k-elems
        int m = i / (KDIM / 8);
        int k = (i % (KDIM / 8)) * 8;

        const float4* xp = reinterpret_cast<const float4*>(x + (size_t)m * KDIM + k);
        float4 v0 = xp[0], v1 = xp[1];
        float v[8] = {v0.x, v0.y, v0.z, v0.w, v1.x, v1.y, v1.z, v1.w};

        uint32_t h[4];
        #pragma unroll
        for (int e = 0; e < 4; e++) {
            __half h0 = __float2half_rn(v[2 * e]);
            __half h1 = __float2half_rn(v[2 * e + 1]);
            h[e] = (uint32_t)__half_as_ushort(h0) | ((uint32_t)__half_as_ushort(h1) << 16);
        }

        int mt = m >> 7, r = m & 127, kt = k >> 5, c = (k & 31) >> 3;
        size_t off = ((size_t)mt * KT + kt) * TILE_G + r * 64 + c * 16;
        *reinterpret_cast<uint4*>(g_a16 + off) = make_uint4(h[0], h[1], h[2], h[3]);
    } else {
        // ---- dequant W ----
        int i = (blockIdx.x - NBLK_CONV) * 256 + threadIdx.x;   // one 8-vector
        int n = i / (INF / 8);
        int k = (i % (INF / 8)) * 8;

        int code = indices[i];
        const float4* cb = reinterpret_cast<const float4*>(codebook) + (size_t)code * 2;
        float4 c0 = cb[0], c1 = cb[1];
        float s = __ldg(&scales[n]);
        float v[8] = {c0.x * s, c0.y * s, c0.z * s, c0.w * s,
                      c1.x * s, c1.y * s, c1.z * s, c1.w * s};

        uint32_t h[4];
        #pragma unroll
        for (int e = 0; e < 4; e++) {
            __half h0 = __float2half_rn(v[2 * e]);
            __half h1 = __float2half_rn(v[2 * e + 1]);
            h[e] = (uint32_t)__half_as_ushort(h0) | ((uint32_t)__half_as_ushort(h1) << 16);
        }

        int nt = n >> 7, r = n & 127, kt = k >> 5, c = (k & 31) >> 3;
        size_t off = ((size_t)nt * KT + kt) * TILE_G + r * 64 + c * 16;
        *reinterpret_cast<uint4*>(g_w16 + off) = make_uint4(h[0], h[1], h[2], h[3]);
    }
}

// ---------------------------------------------------------------------------
// Kernel 2: fp16 HMMA GEMM  C = A16·W16ᵀ   (identical to R13 — proven)
// 128x128 CTA, 64-k pipeline stages (two 32-k sub-steps), NST=3,
// XOR-swizzled smem, 2 CTAs/SM, one wait+sync per 64-k.
// smem swizzle: byte = row*64 + (c ^ ((row>>1)&3))*16
// ---------------------------------------------------------------------------
__global__ void __launch_bounds__(256, 2)
gemm_kernel(float* __restrict__ C) {
    extern __shared__ __align__(1024) uint8_t smem[];
    const uint32_t sb = smem_u32(smem);
    const int tid = threadIdx.x;
    const int lane = tid & 31;
    const int wid = tid >> 5;
    const int wm = wid & 3;       // 4 m-warps (32 rows each)
    const int wn = wid >> 2;      // 2 n-warps (64 cols each)

    // grouped raster: 8 m-tiles per group for L2 reuse
    const int bid = blockIdx.x;
    const int mt = (bid >> 8) * 8 + (bid & 7);
    const int nt = (bid >> 3) & 31;

    const uint8_t* gA = g_a16 + (size_t)mt * KT * TILE_G;
    const uint8_t* gW = g_w16 + (size_t)nt * KT * TILE_G;

    // stage layout: [A(2k) | A(2k+1) | W(2k) | W(2k+1)], 8KB each.
    auto load_stage = [&](int s, int it) {
        #pragma unroll
        for (int j = 0; j < 8; j++) {
            int ch = tid + j * 256;
            int quad = ch >> 9;              // 0:A0 1:A1 2:W0 3:W1
            int row = (ch & 511) >> 2;
            int c = ch & 3;
            int cs = c ^ ((row >> 1) & 3);
            int ktile = 2 * it + (quad & 1);
            const uint8_t* gsrc = ((quad < 2) ? gA : gW) + (size_t)ktile * TILE_G
                                  + row * 64 + c * 16;
            uint32_t sdst = sb + s * STAGE_BYTES + quad * TILE_S
                            + row * 64 + cs * 16;
            cp_async16(sdst, gsrc);
        }
    };

    // prologue: fill NST-1 stages
    #pragma unroll
    for (int s = 0; s < NST - 1; s++) {
        load_stage(s, s);
        CP_COMMIT();
    }
    CP_WAIT(NST - 2);
    __syncthreads();

    float acc[2][8][4];
    #pragma unroll
    for (int mi = 0; mi < 2; mi++)
        #pragma unroll
        for (int n8 = 0; n8 < 8; n8++)
            #pragma unroll
            for (int q = 0; q < 4; q++) acc[mi][n8][q] = 0.0f;

    // per-thread ldmatrix addressing (swizzle select constant per thread)
    const int hb = lane >> 4;                 // 16B half select
    const int rA = (lane & 15);
    const int selA = (rA >> 1) & 3;
    const uint32_t a_row_off = (uint32_t)(wm * 32 + rA) * 64;
    const uint32_t w_row_off = (uint32_t)(wn * 64 + rA) * 64;
    const uint32_t ck0 = (uint32_t)(((0 * 2 + hb) ^ selA) * 16);   // kh=0
    const uint32_t ck1 = (uint32_t)(((1 * 2 + hb) ^ selA) * 16);   // kh=1

    // interleaved sub-step: A ldsm burst, then per-ni (W ldsm -> 8 MMAs)
    auto sub_step = [&](uint32_t sA, uint32_t sW) {
        uint32_t a16[2][2][4], wr[4][2][4];
        #pragma unroll
        for (int mi = 0; mi < 2; mi++) {
            ldsm4(a16[mi][0], sA + a_row_off + mi * 1024 + ck0);
            ldsm4(a16[mi][1], sA + a_row_off + mi * 1024 + ck1);
        }
        #pragma unroll
        for (int ni = 0; ni < 4; ni++) {
            ldsm4(wr[ni][0], sW + w_row_off + ni * 1024 + ck0);
            ldsm4(wr[ni][1], sW + w_row_off + ni * 1024 + ck1);
            #pragma unroll
            for (int kh = 0; kh < 2; kh++)
                #pragma unroll
                for (int mi = 0; mi < 2; mi++)
                    #pragma unroll
                    for (int j = 0; j < 2; j++)
                        mma_f16(acc[mi][2 * ni + j], a16[mi][kh],
                                wr[ni][kh][j], wr[ni][kh][2 + j]);
        }
    };

    int stage = 0;
    for (int it = 0; it < KIT; it++) {
        const uint32_t st = sb + stage * STAGE_BYTES;

        // ---- sub-step 0 (k-tile 2*it) ----
        sub_step(st, st + 2 * TILE_S);

        // ---- issue next stage mid-iteration (drains behind sub-step 1) ----
        const int in_ = it + NST - 1;
        if (in_ < KIT) {
            int sn = stage + NST - 1;
            if (sn >= NST) sn -= NST;
            load_stage(sn, in_);
        }
        CP_COMMIT();

        // ---- sub-step 1 (k-tile 2*it+1) ----
        sub_step(st + TILE_S, st + 3 * TILE_S);

        // ---- advance pipeline (one wait+sync per 64-k) ----
        CP_WAIT(NST - 2);
        __syncthreads();
        if (++stage == NST) stage = 0;
    }

    // epilogue: fragment -> gmem (fp32, 64-bit stores)
    const int row0 = mt * BM + wm * 32 + (lane >> 2);
    const int col0 = nt * BN + wn * 64 + (lane & 3) * 2;
    #pragma unroll
    for (int mi = 0; mi < 2; mi++) {
        #pragma unroll
        for (int n8 = 0; n8 < 8; n8++) {
            float2* p0 = reinterpret_cast<float2*>(
                C + (size_t)(row0 + mi * 16) * NDIM + col0 + n8 * 8);
            float2* p1 = reinterpret_cast<float2*>(
                C + (size_t)(row0 + mi * 16 + 8) * NDIM + col0 + n8 * 8);
            *p0 = make_float2(acc[mi][n8][0], acc[mi][n8][1]);
            *p1 = make_float2(acc[mi][n8][2], acc[mi][n8][3]);
        }
    }
}

// ---------------------------------------------------------------------------
// Launch: fused prep -> gemm  (graph-capturable, no allocs/syncs)
// Inputs (metadata order): x fp32, indices int32, codebook fp32, scales fp32
// ---------------------------------------------------------------------------
extern "C" void kernel_launch(void* const* d_in, const int* in_sizes, int n_in,
                              void* d_out, int out_size) {
    const float* x        = (const float*)d_in[0];
    const int*   indices  = (const int*)d_in[1];
    const float* codebook = (const float*)d_in[2];
    const float* scales   = (const float*)d_in[3];
    float* out = (float*)d_out;

    prep_kernel<<<NBLK_CONV + NBLK_DEQ, 256>>>(x, indices, codebook, scales);

    cudaFuncSetAttribute(gemm_kernel, cudaFuncAttributeMaxDynamicSharedMemorySize,
                         SMEM_TOTAL);
    gemm_kernel<<<MT * NT, 256, SMEM_TOTAL>>>(out);
}